// round 13
// baseline (speedup 1.0000x reference)
#include <cuda_runtime.h>
#include <cuda_bf16.h>
#include <cstdint>

// Problem constants: N=50000, E=600000, IN_DIM=128, HID=256, OUT=128
#define MAXN 50000
#define MAXE 600000
#define DIM 128
#define SCAN_BLK 512
#define MAX_SBLK 128

// Scratch (device globals — no allocation allowed)
__device__ float g_msg[MAXN * DIM];
__device__ int   g_deg[MAXN];
__device__ int   g_off[MAXN];
__device__ int   g_rank[MAXE];              // per-edge rank within dst bucket
__device__ int   g_csr[MAXE];
__device__ int   g_agg[MAX_SBLK];           // scan block aggregates
__device__ int   g_flagS[MAX_SBLK];         // scan publish flags
__device__ __nv_bfloat16 g_Wh[256 * 128];   // hi part of fused W1@W2
__device__ __nv_bfloat16 g_Wl[256 * 128];   // lo part
__device__ float g_b[128];                  // fused bias

static __device__ __forceinline__ uint32_t s2u(const void* p) {
    return (uint32_t)__cvta_generic_to_shared(p);
}

// ---------------------------------------------------------------------------
// Kernel 1: zero degree counters + scan flags
// ---------------------------------------------------------------------------
__global__ void zero_deg(int n) {
    int i = blockIdx.x * blockDim.x + threadIdx.x;
    if (i < n) g_deg[i] = 0;
    if (i < MAX_SBLK) g_flagS[i] = 0;
}

// ---------------------------------------------------------------------------
// Kernel 2: COMBINED weight-fusion || histogram. Blocks 0..255: W rows.
// Block 256: bias. Blocks 257+: histogram, atomic return value = edge rank.
// ---------------------------------------------------------------------------
__global__ void fuse_and_hist(const float* __restrict__ W1, const float* __restrict__ b1,
                              const float* __restrict__ W2, const float* __restrict__ b2,
                              const int* __restrict__ dst, int E) {
    int bb = blockIdx.x;
    int j = threadIdx.x;            // 0..127
    if (bb < 256) {
        int row = bb;
        float acc = 0.f;
        #pragma unroll 4
        for (int k = 0; k < 256; k++)
            acc += W1[row * 256 + k] * W2[k * 128 + j];
        __nv_bfloat16 hi = __float2bfloat16(acc);
        __nv_bfloat16 lo = __float2bfloat16(acc - __bfloat162float(hi));
        g_Wh[row * 128 + j] = hi;
        g_Wl[row * 128 + j] = lo;
    } else if (bb == 256) {
        float acc = b2[j];
        #pragma unroll 4
        for (int k = 0; k < 256; k++)
            acc += b1[k] * W2[k * 128 + j];
        g_b[j] = acc;
    } else {
        int e = (bb - 257) * 128 + j;
        if (e < E) g_rank[e] = atomicAdd(&g_deg[dst[e]], 1);
    }
}

// ---------------------------------------------------------------------------
// Kernel 3: one-launch exclusive scan (decoupled lookback, 98 co-resident blocks)
// ---------------------------------------------------------------------------
__global__ __launch_bounds__(SCAN_BLK) void scan_onepass(int n) {
    __shared__ int sh[SCAN_BLK];
    __shared__ int red[SCAN_BLK];
    int b = blockIdx.x, t = threadIdx.x;
    int i = b * SCAN_BLK + t;
    int v = (i < n) ? g_deg[i] : 0;
    sh[t] = v;
    __syncthreads();
    #pragma unroll
    for (int o = 1; o < SCAN_BLK; o <<= 1) {
        int u = (t >= o) ? sh[t - o] : 0;
        __syncthreads();
        sh[t] += u;
        __syncthreads();
    }
    if (t == 0) {
        g_agg[b] = sh[SCAN_BLK - 1];
        __threadfence();
        atomicExch(&g_flagS[b], 1);
    }
    int part = 0;
    if (t < b) {
        while (atomicAdd(&g_flagS[t], 0) == 0) {}
        part = g_agg[t];
    }
    red[t] = part;
    __syncthreads();
    #pragma unroll
    for (int o = SCAN_BLK / 2; o > 0; o >>= 1) {
        if (t < o) red[t] += red[t + o];
        __syncthreads();
    }
    if (i < n) g_off[i] = red[0] + sh[t] - v;   // exclusive
}

// ---------------------------------------------------------------------------
// Kernel 4: atomic-free CSR fill using precomputed ranks
// ---------------------------------------------------------------------------
__global__ void fill_csr(const int* __restrict__ src, const int* __restrict__ dst, int E) {
    int e = blockIdx.x * blockDim.x + threadIdx.x;
    if (e >= E) return;
    g_csr[g_off[dst[e]] + g_rank[e]] = src[e];
}

// ---------------------------------------------------------------------------
// Kernel 5: gather + mean. One warp per node; explicit 4-deep load staging
// (single-variable change vs measured-110.4 baseline: raise MLP in the
// dynamic-bound inner loop that ptxas cannot unroll).
// ---------------------------------------------------------------------------
__global__ void gather_csr(const float* __restrict__ h, int n) {
    int warp = (blockIdx.x * blockDim.x + threadIdx.x) >> 5;
    int lane = threadIdx.x & 31;
    if (warp >= n) return;
    int beg = g_off[warp];
    int deg = g_deg[warp];
    float4 acc = make_float4(0.f, 0.f, 0.f, 0.f);

    for (int i = 0; i < deg; i += 32) {
        int m = min(32, deg - i);
        int idx = (lane < m) ? g_csr[beg + i + lane] : 0;
        int j = 0;
        // 4-deep stage: batch shfls, then 4 independent LDG.128, then adds
        for (; j + 4 <= m; j += 4) {
            int s0 = __shfl_sync(0xffffffff, idx, j);
            int s1 = __shfl_sync(0xffffffff, idx, j + 1);
            int s2 = __shfl_sync(0xffffffff, idx, j + 2);
            int s3 = __shfl_sync(0xffffffff, idx, j + 3);
            float4 v0 = reinterpret_cast<const float4*>(h)[(size_t)s0 * (DIM / 4) + lane];
            float4 v1 = reinterpret_cast<const float4*>(h)[(size_t)s1 * (DIM / 4) + lane];
            float4 v2 = reinterpret_cast<const float4*>(h)[(size_t)s2 * (DIM / 4) + lane];
            float4 v3 = reinterpret_cast<const float4*>(h)[(size_t)s3 * (DIM / 4) + lane];
            acc.x += (v0.x + v1.x) + (v2.x + v3.x);
            acc.y += (v0.y + v1.y) + (v2.y + v3.y);
            acc.z += (v0.z + v1.z) + (v2.z + v3.z);
            acc.w += (v0.w + v1.w) + (v2.w + v3.w);
        }
        for (; j < m; j++) {
            int s = __shfl_sync(0xffffffff, idx, j);
            float4 v = reinterpret_cast<const float4*>(h)[(size_t)s * (DIM / 4) + lane];
            acc.x += v.x; acc.y += v.y; acc.z += v.z; acc.w += v.w;
        }
    }
    float inv = 1.0f / fmaxf((float)deg, 1.0f);
    acc.x *= inv; acc.y *= inv; acc.z *= inv; acc.w *= inv;
    reinterpret_cast<float4*>(g_msg)[(size_t)warp * (DIM / 4) + lane] = acc;
}

// ---------------------------------------------------------------------------
// Kernel 6: tensor-core GEMM + bias + relu (bf16 3-way split, mma.sync).
// 64x128 block tile, warp tile 32x32, 3 blocks/SM (measured-good R12 config).
// ---------------------------------------------------------------------------
#define GBM 64
#define GBK 32
#define LDA 40
#define LDB 136

#define MMA_B16(d, a, b)                                                        \
    asm volatile("mma.sync.aligned.m16n8k16.row.col.f32.bf16.bf16.f32 "         \
                 "{%0,%1,%2,%3}, {%4,%5,%6,%7}, {%8,%9}, {%0,%1,%2,%3};"        \
                 : "+f"(d[0]), "+f"(d[1]), "+f"(d[2]), "+f"(d[3])               \
                 : "r"(a[0]), "r"(a[1]), "r"(a[2]), "r"(a[3]),                  \
                   "r"(b[0]), "r"(b[1]))

__global__ __launch_bounds__(256, 3) void fused_gemm_mma(const float* __restrict__ h,
                                                         float* __restrict__ out, int M) {
    __shared__ __nv_bfloat16 Ah[GBM * LDA], Al[GBM * LDA];
    __shared__ __nv_bfloat16 Bh[GBK * LDB], Bl[GBK * LDB];

    int tid = threadIdx.x;
    int lane = tid & 31;
    int warp = tid >> 5;
    int wm = (warp >> 2) * 32;
    int wn = (warp & 3) * 32;
    int row0 = blockIdx.x * GBM;

    float acc[2][4][4];
    #pragma unroll
    for (int mt = 0; mt < 2; mt++)
        #pragma unroll
        for (int nt = 0; nt < 4; nt++)
            #pragma unroll
            for (int r = 0; r < 4; r++) acc[mt][nt][r] = 0.f;

    for (int kc = 0; kc < 8; kc++) {
        int k0 = kc * GBK;
        const float* Abase = (k0 < 128) ? (h + k0) : (g_msg + (k0 - 128));

        #pragma unroll
        for (int l = 0; l < 2; l++) {
            int idx = tid + l * 256;
            int r = idx >> 3;
            int c = (idx & 7) * 4;
            float4 v = make_float4(0.f, 0.f, 0.f, 0.f);
            int gr = row0 + r;
            if (gr < M) v = *reinterpret_cast<const float4*>(Abase + (size_t)gr * DIM + c);
            float f[4] = {v.x, v.y, v.z, v.w};
            __nv_bfloat16 h0 = __float2bfloat16(f[0]);
            __nv_bfloat16 h1 = __float2bfloat16(f[1]);
            __nv_bfloat16 h2 = __float2bfloat16(f[2]);
            __nv_bfloat16 h3 = __float2bfloat16(f[3]);
            __nv_bfloat162 hp0 = __nv_bfloat162(h0, h1);
            __nv_bfloat162 hp1 = __nv_bfloat162(h2, h3);
            __nv_bfloat162 lp0 = __nv_bfloat162(__float2bfloat16(f[0] - __bfloat162float(h0)),
                                                __float2bfloat16(f[1] - __bfloat162float(h1)));
            __nv_bfloat162 lp1 = __nv_bfloat162(__float2bfloat16(f[2] - __bfloat162float(h2)),
                                                __float2bfloat16(f[3] - __bfloat162float(h3)));
            *reinterpret_cast<__nv_bfloat162*>(&Ah[r * LDA + c])     = hp0;
            *reinterpret_cast<__nv_bfloat162*>(&Ah[r * LDA + c + 2]) = hp1;
            *reinterpret_cast<__nv_bfloat162*>(&Al[r * LDA + c])     = lp0;
            *reinterpret_cast<__nv_bfloat162*>(&Al[r * LDA + c + 2]) = lp1;
        }
        #pragma unroll
        for (int l = 0; l < 4; l++) {
            int idx = tid + l * 256;
            int r = idx >> 5;
            int c = (idx & 31) * 4;
            uint2 vh = *reinterpret_cast<const uint2*>(&g_Wh[(size_t)(k0 + r) * 128 + c]);
            uint2 vl = *reinterpret_cast<const uint2*>(&g_Wl[(size_t)(k0 + r) * 128 + c]);
            *reinterpret_cast<uint2*>(&Bh[r * LDB + c]) = vh;
            *reinterpret_cast<uint2*>(&Bl[r * LDB + c]) = vl;
        }
        __syncthreads();

        #pragma unroll
        for (int ks = 0; ks < 2; ks++) {
            uint32_t ah[2][4], al[2][4], bh[4][2], bl[4][2];
            #pragma unroll
            for (int mt = 0; mt < 2; mt++) {
                int r = wm + mt * 16 + (lane & 15);
                int eo = r * LDA + ks * 16 + ((lane >> 4) * 8);
                uint32_t ad = s2u(&Ah[eo]);
                asm volatile("ldmatrix.sync.aligned.m8n8.x4.shared.b16 {%0,%1,%2,%3}, [%4];"
                             : "=r"(ah[mt][0]), "=r"(ah[mt][1]), "=r"(ah[mt][2]), "=r"(ah[mt][3])
                             : "r"(ad));
                uint32_t ad2 = s2u(&Al[eo]);
                asm volatile("ldmatrix.sync.aligned.m8n8.x4.shared.b16 {%0,%1,%2,%3}, [%4];"
                             : "=r"(al[mt][0]), "=r"(al[mt][1]), "=r"(al[mt][2]), "=r"(al[mt][3])
                             : "r"(ad2));
            }
            #pragma unroll
            for (int nt = 0; nt < 4; nt++) {
                int kr = ks * 16 + (lane & 15);
                int eo = kr * LDB + wn + nt * 8;
                uint32_t bd = s2u(&Bh[eo]);
                asm volatile("ldmatrix.sync.aligned.m8n8.x2.trans.shared.b16 {%0,%1}, [%2];"
                             : "=r"(bh[nt][0]), "=r"(bh[nt][1]) : "r"(bd));
                uint32_t bd2 = s2u(&Bl[eo]);
                asm volatile("ldmatrix.sync.aligned.m8n8.x2.trans.shared.b16 {%0,%1}, [%2];"
                             : "=r"(bl[nt][0]), "=r"(bl[nt][1]) : "r"(bd2));
            }
            #pragma unroll
            for (int mt = 0; mt < 2; mt++)
                #pragma unroll
                for (int nt = 0; nt < 4; nt++) {
                    MMA_B16(acc[mt][nt], ah[mt], bh[nt]);
                    MMA_B16(acc[mt][nt], ah[mt], bl[nt]);
                    MMA_B16(acc[mt][nt], al[mt], bh[nt]);
                }
        }
        __syncthreads();
    }

    #pragma unroll
    for (int mt = 0; mt < 2; mt++) {
        int r0 = row0 + wm + mt * 16 + (lane >> 2);
        #pragma unroll
        for (int nt = 0; nt < 4; nt++) {
            int col = wn + nt * 8 + (lane & 3) * 2;
            float b0 = g_b[col], b1 = g_b[col + 1];
            if (r0 < M) {
                float2 o;
                o.x = fmaxf(acc[mt][nt][0] + b0, 0.f);
                o.y = fmaxf(acc[mt][nt][1] + b1, 0.f);
                *reinterpret_cast<float2*>(&out[(size_t)r0 * DIM + col]) = o;
            }
            int r1 = r0 + 8;
            if (r1 < M) {
                float2 o;
                o.x = fmaxf(acc[mt][nt][2] + b0, 0.f);
                o.y = fmaxf(acc[mt][nt][3] + b1, 0.f);
                *reinterpret_cast<float2*>(&out[(size_t)r1 * DIM + col]) = o;
            }
        }
    }
}

// ---------------------------------------------------------------------------
extern "C" void kernel_launch(void* const* d_in, const int* in_sizes, int n_in,
                              void* d_out, int out_size) {
    const float* h  = (const float*)d_in[0];
    const int* src  = (const int*)d_in[1];
    const int* dst  = (const int*)d_in[2];
    const float* W1 = (const float*)d_in[3];
    const float* b1 = (const float*)d_in[4];
    const float* W2 = (const float*)d_in[5];
    const float* b2 = (const float*)d_in[6];
    float* out = (float*)d_out;

    int N = in_sizes[0] / DIM;
    int E = in_sizes[1];
    int sblocks = (N + SCAN_BLK - 1) / SCAN_BLK;   // 98
    int hblocks = (E + 127) / 128;                 // 4688

    zero_deg<<<(N + 255) / 256, 256>>>(N);
    fuse_and_hist<<<257 + hblocks, 128>>>(W1, b1, W2, b2, dst, E);
    scan_onepass<<<sblocks, SCAN_BLK>>>(N);
    fill_csr<<<(E + 255) / 256, 256>>>(src, dst, E);

    long long gthreads = (long long)N * 32;
    gather_csr<<<(int)((gthreads + 255) / 256), 256>>>(h, N);

    fused_gemm_mma<<<(N + GBM - 1) / GBM, 256>>>(h, out, N);
}

// round 14
// speedup vs baseline: 1.1061x; 1.1061x over previous
#include <cuda_runtime.h>
#include <cuda_bf16.h>
#include <cstdint>

// Problem constants: N=50000, E=600000, IN_DIM=128, HID=256, OUT=128
#define MAXN 50000
#define MAXE 600000
#define DIM 128
#define SCAN_BLK 512
#define MAX_SBLK 128

// Scratch (device globals — no allocation allowed)
__device__ float g_msg[MAXN * DIM];
__device__ float g_partial[MAXN * DIM];     // h @ W[0:128] partial accumulators
__device__ int   g_deg[MAXN];
__device__ int   g_off[MAXN];
__device__ int   g_rank[MAXE];
__device__ int   g_csr[MAXE];
__device__ int   g_agg[MAX_SBLK];
__device__ int   g_flagS[MAX_SBLK];
__device__ __nv_bfloat16 g_Wh[256 * 128];   // hi part of fused W1@W2
__device__ __nv_bfloat16 g_Wl[256 * 128];   // lo part
__device__ float g_b[128];                  // fused bias

static __device__ __forceinline__ uint32_t s2u(const void* p) {
    return (uint32_t)__cvta_generic_to_shared(p);
}

// ---------------------------------------------------------------------------
// Kernel 1 (stream A): zero degree counters + scan flags
// ---------------------------------------------------------------------------
__global__ void zero_deg(int n) {
    int i = blockIdx.x * blockDim.x + threadIdx.x;
    if (i < n) g_deg[i] = 0;
    if (i < MAX_SBLK) g_flagS[i] = 0;
}

// ---------------------------------------------------------------------------
// Kernel 2 (stream B): weight fusion. Blocks 0..255: W rows. Block 256: bias.
// ---------------------------------------------------------------------------
__global__ void fuse_weights(const float* __restrict__ W1, const float* __restrict__ b1,
                             const float* __restrict__ W2, const float* __restrict__ b2) {
    int row = blockIdx.x;
    int j = threadIdx.x;            // 0..127
    if (row < 256) {
        float acc = 0.f;
        #pragma unroll 4
        for (int k = 0; k < 256; k++)
            acc += W1[row * 256 + k] * W2[k * 128 + j];
        __nv_bfloat16 hi = __float2bfloat16(acc);
        __nv_bfloat16 lo = __float2bfloat16(acc - __bfloat162float(hi));
        g_Wh[row * 128 + j] = hi;
        g_Wl[row * 128 + j] = lo;
    } else {
        float acc = b2[j];
        #pragma unroll 4
        for (int k = 0; k < 256; k++)
            acc += b1[k] * W2[k * 128 + j];
        g_b[j] = acc;
    }
}

// ---------------------------------------------------------------------------
// Kernel 3 (stream A): degree histogram; atomic return = edge rank
// ---------------------------------------------------------------------------
__global__ void histogram(const int* __restrict__ dst, int E) {
    int e = blockIdx.x * blockDim.x + threadIdx.x;
    if (e < E) g_rank[e] = atomicAdd(&g_deg[dst[e]], 1);
}

// ---------------------------------------------------------------------------
// Kernel 4 (stream A): one-launch exclusive scan (decoupled lookback)
// ---------------------------------------------------------------------------
__global__ __launch_bounds__(SCAN_BLK) void scan_onepass(int n) {
    __shared__ int sh[SCAN_BLK];
    __shared__ int red[SCAN_BLK];
    int b = blockIdx.x, t = threadIdx.x;
    int i = b * SCAN_BLK + t;
    int v = (i < n) ? g_deg[i] : 0;
    sh[t] = v;
    __syncthreads();
    #pragma unroll
    for (int o = 1; o < SCAN_BLK; o <<= 1) {
        int u = (t >= o) ? sh[t - o] : 0;
        __syncthreads();
        sh[t] += u;
        __syncthreads();
    }
    if (t == 0) {
        g_agg[b] = sh[SCAN_BLK - 1];
        __threadfence();
        atomicExch(&g_flagS[b], 1);
    }
    int part = 0;
    if (t < b) {
        while (atomicAdd(&g_flagS[t], 0) == 0) {}
        part = g_agg[t];
    }
    red[t] = part;
    __syncthreads();
    #pragma unroll
    for (int o = SCAN_BLK / 2; o > 0; o >>= 1) {
        if (t < o) red[t] += red[t + o];
        __syncthreads();
    }
    if (i < n) g_off[i] = red[0] + sh[t] - v;   // exclusive
}

// ---------------------------------------------------------------------------
// Kernel 5 (stream A): atomic-free CSR fill
// ---------------------------------------------------------------------------
__global__ void fill_csr(const int* __restrict__ src, const int* __restrict__ dst, int E) {
    int e = blockIdx.x * blockDim.x + threadIdx.x;
    if (e >= E) return;
    g_csr[g_off[dst[e]] + g_rank[e]] = src[e];
}

// ---------------------------------------------------------------------------
// Kernel 6 (stream A): gather + mean (R12 measured-best simple loop)
// ---------------------------------------------------------------------------
__global__ void gather_csr(const float* __restrict__ h, int n) {
    int warp = (blockIdx.x * blockDim.x + threadIdx.x) >> 5;
    int lane = threadIdx.x & 31;
    if (warp >= n) return;
    int beg = g_off[warp];
    int deg = g_deg[warp];
    float4 acc = make_float4(0.f, 0.f, 0.f, 0.f);

    for (int i = 0; i < deg; i += 32) {
        int idx = (i + lane < deg) ? g_csr[beg + i + lane] : 0;
        int m = min(32, deg - i);
        #pragma unroll 4
        for (int j = 0; j < m; j++) {
            int s = __shfl_sync(0xffffffff, idx, j);
            float4 v = reinterpret_cast<const float4*>(h)[(size_t)s * (DIM / 4) + lane];
            acc.x += v.x; acc.y += v.y; acc.z += v.z; acc.w += v.w;
        }
    }
    float inv = 1.0f / fmaxf((float)deg, 1.0f);
    acc.x *= inv; acc.y *= inv; acc.z *= inv; acc.w *= inv;
    reinterpret_cast<float4*>(g_msg)[(size_t)warp * (DIM / 4) + lane] = acc;
}

// ---------------------------------------------------------------------------
// GEMM common (R12 64x128 tile, bf16 3-way split)
// ---------------------------------------------------------------------------
#define GBM 64
#define GBK 32
#define LDA 40
#define LDB 136

#define MMA_B16(d, a, b)                                                        \
    asm volatile("mma.sync.aligned.m16n8k16.row.col.f32.bf16.bf16.f32 "         \
                 "{%0,%1,%2,%3}, {%4,%5,%6,%7}, {%8,%9}, {%0,%1,%2,%3};"        \
                 : "+f"(d[0]), "+f"(d[1]), "+f"(d[2]), "+f"(d[3])               \
                 : "r"(a[0]), "r"(a[1]), "r"(a[2]), "r"(a[3]),                  \
                   "r"(b[0]), "r"(b[1]))

// Shared mainloop body over k-chunks [kcLo, kcHi); Asrc has row stride DIM.
template <bool ADD_PARTIAL>
__device__ __forceinline__ void gemm_half(const float* __restrict__ Asrc,
                                          float* __restrict__ outp, int M,
                                          int kcLo, int kcHi) {
    __shared__ __nv_bfloat16 Ah[GBM * LDA], Al[GBM * LDA];
    __shared__ __nv_bfloat16 Bh[GBK * LDB], Bl[GBK * LDB];

    int tid = threadIdx.x;
    int lane = tid & 31;
    int warp = tid >> 5;
    int wm = (warp >> 2) * 32;
    int wn = (warp & 3) * 32;
    int row0 = blockIdx.x * GBM;

    float acc[2][4][4];
    #pragma unroll
    for (int mt = 0; mt < 2; mt++)
        #pragma unroll
        for (int nt = 0; nt < 4; nt++)
            #pragma unroll
            for (int r = 0; r < 4; r++) acc[mt][nt][r] = 0.f;

    for (int kc = kcLo; kc < kcHi; kc++) {
        int k0 = kc * GBK;                 // global k (for B)
        int ka = k0 - kcLo * GBK;          // local k within Asrc (stride DIM)

        #pragma unroll
        for (int l = 0; l < 2; l++) {
            int idx = tid + l * 256;
            int r = idx >> 3;
            int c = (idx & 7) * 4;
            float4 v = make_float4(0.f, 0.f, 0.f, 0.f);
            int gr = row0 + r;
            if (gr < M) v = *reinterpret_cast<const float4*>(Asrc + (size_t)gr * DIM + ka + c);
            float f[4] = {v.x, v.y, v.z, v.w};
            __nv_bfloat16 h0 = __float2bfloat16(f[0]);
            __nv_bfloat16 h1 = __float2bfloat16(f[1]);
            __nv_bfloat16 h2 = __float2bfloat16(f[2]);
            __nv_bfloat16 h3 = __float2bfloat16(f[3]);
            __nv_bfloat162 hp0 = __nv_bfloat162(h0, h1);
            __nv_bfloat162 hp1 = __nv_bfloat162(h2, h3);
            __nv_bfloat162 lp0 = __nv_bfloat162(__float2bfloat16(f[0] - __bfloat162float(h0)),
                                                __float2bfloat16(f[1] - __bfloat162float(h1)));
            __nv_bfloat162 lp1 = __nv_bfloat162(__float2bfloat16(f[2] - __bfloat162float(h2)),
                                                __float2bfloat16(f[3] - __bfloat162float(h3)));
            *reinterpret_cast<__nv_bfloat162*>(&Ah[r * LDA + c])     = hp0;
            *reinterpret_cast<__nv_bfloat162*>(&Ah[r * LDA + c + 2]) = hp1;
            *reinterpret_cast<__nv_bfloat162*>(&Al[r * LDA + c])     = lp0;
            *reinterpret_cast<__nv_bfloat162*>(&Al[r * LDA + c + 2]) = lp1;
        }
        #pragma unroll
        for (int l = 0; l < 4; l++) {
            int idx = tid + l * 256;
            int r = idx >> 5;
            int c = (idx & 31) * 4;
            uint2 vh = *reinterpret_cast<const uint2*>(&g_Wh[(size_t)(k0 + r) * 128 + c]);
            uint2 vl = *reinterpret_cast<const uint2*>(&g_Wl[(size_t)(k0 + r) * 128 + c]);
            *reinterpret_cast<uint2*>(&Bh[r * LDB + c]) = vh;
            *reinterpret_cast<uint2*>(&Bl[r * LDB + c]) = vl;
        }
        __syncthreads();

        #pragma unroll
        for (int ks = 0; ks < 2; ks++) {
            uint32_t ah[2][4], al[2][4], bh[4][2], bl[4][2];
            #pragma unroll
            for (int mt = 0; mt < 2; mt++) {
                int r = wm + mt * 16 + (lane & 15);
                int eo = r * LDA + ks * 16 + ((lane >> 4) * 8);
                uint32_t ad = s2u(&Ah[eo]);
                asm volatile("ldmatrix.sync.aligned.m8n8.x4.shared.b16 {%0,%1,%2,%3}, [%4];"
                             : "=r"(ah[mt][0]), "=r"(ah[mt][1]), "=r"(ah[mt][2]), "=r"(ah[mt][3])
                             : "r"(ad));
                uint32_t ad2 = s2u(&Al[eo]);
                asm volatile("ldmatrix.sync.aligned.m8n8.x4.shared.b16 {%0,%1,%2,%3}, [%4];"
                             : "=r"(al[mt][0]), "=r"(al[mt][1]), "=r"(al[mt][2]), "=r"(al[mt][3])
                             : "r"(ad2));
            }
            #pragma unroll
            for (int nt = 0; nt < 4; nt++) {
                int kr = ks * 16 + (lane & 15);
                int eo = kr * LDB + wn + nt * 8;
                uint32_t bd = s2u(&Bh[eo]);
                asm volatile("ldmatrix.sync.aligned.m8n8.x2.trans.shared.b16 {%0,%1}, [%2];"
                             : "=r"(bh[nt][0]), "=r"(bh[nt][1]) : "r"(bd));
                uint32_t bd2 = s2u(&Bl[eo]);
                asm volatile("ldmatrix.sync.aligned.m8n8.x2.trans.shared.b16 {%0,%1}, [%2];"
                             : "=r"(bl[nt][0]), "=r"(bl[nt][1]) : "r"(bd2));
            }
            #pragma unroll
            for (int mt = 0; mt < 2; mt++)
                #pragma unroll
                for (int nt = 0; nt < 4; nt++) {
                    MMA_B16(acc[mt][nt], ah[mt], bh[nt]);
                    MMA_B16(acc[mt][nt], ah[mt], bl[nt]);
                    MMA_B16(acc[mt][nt], al[mt], bh[nt]);
                }
        }
        __syncthreads();
    }

    // epilogue
    #pragma unroll
    for (int mt = 0; mt < 2; mt++) {
        int r0 = row0 + wm + mt * 16 + (lane >> 2);
        #pragma unroll
        for (int nt = 0; nt < 4; nt++) {
            int col = wn + nt * 8 + (lane & 3) * 2;
            if (ADD_PARTIAL) {
                float b0 = g_b[col], b1 = g_b[col + 1];
                if (r0 < M) {
                    float2 p = *reinterpret_cast<const float2*>(&g_partial[(size_t)r0 * DIM + col]);
                    float2 o;
                    o.x = fmaxf(acc[mt][nt][0] + p.x + b0, 0.f);
                    o.y = fmaxf(acc[mt][nt][1] + p.y + b1, 0.f);
                    *reinterpret_cast<float2*>(&outp[(size_t)r0 * DIM + col]) = o;
                }
                int r1 = r0 + 8;
                if (r1 < M) {
                    float2 p = *reinterpret_cast<const float2*>(&g_partial[(size_t)r1 * DIM + col]);
                    float2 o;
                    o.x = fmaxf(acc[mt][nt][2] + p.x + b0, 0.f);
                    o.y = fmaxf(acc[mt][nt][3] + p.y + b1, 0.f);
                    *reinterpret_cast<float2*>(&outp[(size_t)r1 * DIM + col]) = o;
                }
            } else {
                if (r0 < M) {
                    float2 o = make_float2(acc[mt][nt][0], acc[mt][nt][1]);
                    *reinterpret_cast<float2*>(&outp[(size_t)r0 * DIM + col]) = o;
                }
                int r1 = r0 + 8;
                if (r1 < M) {
                    float2 o = make_float2(acc[mt][nt][2], acc[mt][nt][3]);
                    *reinterpret_cast<float2*>(&outp[(size_t)r1 * DIM + col]) = o;
                }
            }
        }
    }
}

// Kernel 7 (stream B): partial = h @ W[0:128]  (independent of aggregation)
__global__ __launch_bounds__(256, 3) void gemm_h(const float* __restrict__ h, int M) {
    gemm_half<false>(h, g_partial, M, 0, 4);
}

// Kernel 8 (join): out = relu(partial + msg @ W[128:256] + b)
__global__ __launch_bounds__(256, 3) void gemm_msg(float* __restrict__ out, int M) {
    gemm_half<true>(g_msg, out, M, 4, 8);
}

// ---------------------------------------------------------------------------
extern "C" void kernel_launch(void* const* d_in, const int* in_sizes, int n_in,
                              void* d_out, int out_size) {
    const float* h  = (const float*)d_in[0];
    const int* src  = (const int*)d_in[1];
    const int* dst  = (const int*)d_in[2];
    const float* W1 = (const float*)d_in[3];
    const float* b1 = (const float*)d_in[4];
    const float* W2 = (const float*)d_in[5];
    const float* b2 = (const float*)d_in[6];
    float* out = (float*)d_out;

    int N = in_sizes[0] / DIM;
    int E = in_sizes[1];
    int sblocks = (N + SCAN_BLK - 1) / SCAN_BLK;   // 98
    int gemmblocks = (N + GBM - 1) / GBM;          // 782

    // Fork a second stream for the aggregation-independent branch
    // (fuse_weights -> gemm_h), overlapped with zero->hist->scan->fill->gather.
    cudaStream_t sB;
    cudaEvent_t eFork, eJoin;
    cudaStreamCreateWithFlags(&sB, cudaStreamNonBlocking);
    cudaEventCreateWithFlags(&eFork, cudaEventDisableTiming);
    cudaEventCreateWithFlags(&eJoin, cudaEventDisableTiming);

    cudaEventRecord(eFork, 0);
    cudaStreamWaitEvent(sB, eFork, 0);

    // Stream B: weight fusion + h-half GEMM
    fuse_weights<<<257, 128, 0, sB>>>(W1, b1, W2, b2);
    gemm_h<<<gemmblocks, 256, 0, sB>>>(h, N);
    cudaEventRecord(eJoin, sB);

    // Stream A (default): aggregation chain
    zero_deg<<<(N + 255) / 256, 256>>>(N);
    histogram<<<(E + 255) / 256, 256>>>(dst, E);
    scan_onepass<<<sblocks, SCAN_BLK>>>(N);
    fill_csr<<<(E + 255) / 256, 256>>>(src, dst, E);
    long long gthreads = (long long)N * 32;
    gather_csr<<<(int)((gthreads + 255) / 256), 256>>>(h, N);

    // Join and finish: msg-half GEMM + partial + bias + relu
    cudaStreamWaitEvent(0, eJoin, 0);
    gemm_msg<<<gemmblocks, 256>>>(out, N);
}

// round 15
// speedup vs baseline: 1.1774x; 1.0645x over previous
#include <cuda_runtime.h>
#include <cuda_bf16.h>
#include <cstdint>

// Problem constants: N=50000, E=600000, IN_DIM=128, HID=256, OUT=128
#define MAXN 50000
#define MAXE 600000
#define DIM 128
#define SCAN_BLK 512
#define MAX_SBLK 128

// Scratch (device globals — zero-initialized at module load; the cleanup
// kernel restores the zero invariant at the end of every execution)
__device__ float g_msg[MAXN * DIM];
__device__ float g_partial[MAXN * DIM];     // h @ W[0:128]
__device__ int   g_deg[MAXN];
__device__ int   g_off[MAXN];
__device__ int   g_rank[MAXE];
__device__ int   g_csr[MAXE];
__device__ int   g_agg[MAX_SBLK];
__device__ int   g_flagS[MAX_SBLK];
__device__ __nv_bfloat16 g_Wh[256 * 128];
__device__ __nv_bfloat16 g_Wl[256 * 128];
__device__ float g_b[128];

static __device__ __forceinline__ uint32_t s2u(const void* p) {
    return (uint32_t)__cvta_generic_to_shared(p);
}

// ---------------------------------------------------------------------------
// Kernel (stream B): weight fusion. Blocks 0..255: W rows. Block 256: bias.
// ---------------------------------------------------------------------------
__global__ void fuse_weights(const float* __restrict__ W1, const float* __restrict__ b1,
                             const float* __restrict__ W2, const float* __restrict__ b2) {
    int row = blockIdx.x;
    int j = threadIdx.x;
    if (row < 256) {
        float acc = 0.f;
        #pragma unroll 4
        for (int k = 0; k < 256; k++)
            acc += W1[row * 256 + k] * W2[k * 128 + j];
        __nv_bfloat16 hi = __float2bfloat16(acc);
        __nv_bfloat16 lo = __float2bfloat16(acc - __bfloat162float(hi));
        g_Wh[row * 128 + j] = hi;
        g_Wl[row * 128 + j] = lo;
    } else {
        float acc = b2[j];
        #pragma unroll 4
        for (int k = 0; k < 256; k++)
            acc += b1[k] * W2[k * 128 + j];
        g_b[j] = acc;
    }
}

// ---------------------------------------------------------------------------
// Kernel (stream A): degree histogram; atomic return = edge rank.
// Relies on g_deg == 0 (zero-init first run; cleanup kernel thereafter).
// ---------------------------------------------------------------------------
__global__ void histogram(const int* __restrict__ dst, int E) {
    int e = blockIdx.x * blockDim.x + threadIdx.x;
    if (e < E) g_rank[e] = atomicAdd(&g_deg[dst[e]], 1);
}

// ---------------------------------------------------------------------------
// Kernel (stream A): one-launch exclusive scan (decoupled lookback).
// Relies on g_flagS == 0 (zero-init / cleanup).
// ---------------------------------------------------------------------------
__global__ __launch_bounds__(SCAN_BLK) void scan_onepass(int n) {
    __shared__ int sh[SCAN_BLK];
    __shared__ int red[SCAN_BLK];
    int b = blockIdx.x, t = threadIdx.x;
    int i = b * SCAN_BLK + t;
    int v = (i < n) ? g_deg[i] : 0;
    sh[t] = v;
    __syncthreads();
    #pragma unroll
    for (int o = 1; o < SCAN_BLK; o <<= 1) {
        int u = (t >= o) ? sh[t - o] : 0;
        __syncthreads();
        sh[t] += u;
        __syncthreads();
    }
    if (t == 0) {
        g_agg[b] = sh[SCAN_BLK - 1];
        __threadfence();
        atomicExch(&g_flagS[b], 1);
    }
    int part = 0;
    if (t < b) {
        while (atomicAdd(&g_flagS[t], 0) == 0) {}
        part = g_agg[t];
    }
    red[t] = part;
    __syncthreads();
    #pragma unroll
    for (int o = SCAN_BLK / 2; o > 0; o >>= 1) {
        if (t < o) red[t] += red[t + o];
        __syncthreads();
    }
    if (i < n) g_off[i] = red[0] + sh[t] - v;
}

// ---------------------------------------------------------------------------
// Kernel (stream A): atomic-free CSR fill
// ---------------------------------------------------------------------------
__global__ void fill_csr(const int* __restrict__ src, const int* __restrict__ dst, int E) {
    int e = blockIdx.x * blockDim.x + threadIdx.x;
    if (e >= E) return;
    g_csr[g_off[dst[e]] + g_rank[e]] = src[e];
}

// ---------------------------------------------------------------------------
// Kernel (stream A): gather + mean over node range [n0, n1). One warp/node.
// ---------------------------------------------------------------------------
__global__ void gather_csr(const float* __restrict__ h, int n0, int n1) {
    int warp = n0 + ((blockIdx.x * blockDim.x + threadIdx.x) >> 5);
    int lane = threadIdx.x & 31;
    if (warp >= n1) return;
    int beg = g_off[warp];
    int deg = g_deg[warp];
    float4 acc = make_float4(0.f, 0.f, 0.f, 0.f);

    for (int i = 0; i < deg; i += 32) {
        int idx = (i + lane < deg) ? g_csr[beg + i + lane] : 0;
        int m = min(32, deg - i);
        #pragma unroll 4
        for (int j = 0; j < m; j++) {
            int s = __shfl_sync(0xffffffff, idx, j);
            float4 v = reinterpret_cast<const float4*>(h)[(size_t)s * (DIM / 4) + lane];
            acc.x += v.x; acc.y += v.y; acc.z += v.z; acc.w += v.w;
        }
    }
    float inv = 1.0f / fmaxf((float)deg, 1.0f);
    acc.x *= inv; acc.y *= inv; acc.z *= inv; acc.w *= inv;
    reinterpret_cast<float4*>(g_msg)[(size_t)warp * (DIM / 4) + lane] = acc;
}

// ---------------------------------------------------------------------------
// Kernel (stream B, end): restore zero invariant for next execution
// ---------------------------------------------------------------------------
__global__ void cleanup(int n) {
    int i = blockIdx.x * blockDim.x + threadIdx.x;
    if (i < n) g_deg[i] = 0;
    if (i < MAX_SBLK) g_flagS[i] = 0;
}

// ---------------------------------------------------------------------------
// GEMM common (R12 64x128 tile, bf16 3-way split), block offset blk0
// ---------------------------------------------------------------------------
#define GBM 64
#define GBK 32
#define LDA 40
#define LDB 136

#define MMA_B16(d, a, b)                                                        \
    asm volatile("mma.sync.aligned.m16n8k16.row.col.f32.bf16.bf16.f32 "         \
                 "{%0,%1,%2,%3}, {%4,%5,%6,%7}, {%8,%9}, {%0,%1,%2,%3};"        \
                 : "+f"(d[0]), "+f"(d[1]), "+f"(d[2]), "+f"(d[3])               \
                 : "r"(a[0]), "r"(a[1]), "r"(a[2]), "r"(a[3]),                  \
                   "r"(b[0]), "r"(b[1]))

template <bool ADD_PARTIAL>
__device__ __forceinline__ void gemm_half(const float* __restrict__ Asrc,
                                          float* __restrict__ outp, int M,
                                          int kcLo, int kcHi, int blk0) {
    __shared__ __nv_bfloat16 Ah[GBM * LDA], Al[GBM * LDA];
    __shared__ __nv_bfloat16 Bh[GBK * LDB], Bl[GBK * LDB];

    int tid = threadIdx.x;
    int lane = tid & 31;
    int warp = tid >> 5;
    int wm = (warp >> 2) * 32;
    int wn = (warp & 3) * 32;
    int row0 = (blockIdx.x + blk0) * GBM;

    float acc[2][4][4];
    #pragma unroll
    for (int mt = 0; mt < 2; mt++)
        #pragma unroll
        for (int nt = 0; nt < 4; nt++)
            #pragma unroll
            for (int r = 0; r < 4; r++) acc[mt][nt][r] = 0.f;

    for (int kc = kcLo; kc < kcHi; kc++) {
        int k0 = kc * GBK;
        int ka = k0 - kcLo * GBK;

        #pragma unroll
        for (int l = 0; l < 2; l++) {
            int idx = tid + l * 256;
            int r = idx >> 3;
            int c = (idx & 7) * 4;
            float4 v = make_float4(0.f, 0.f, 0.f, 0.f);
            int gr = row0 + r;
            if (gr < M) v = *reinterpret_cast<const float4*>(Asrc + (size_t)gr * DIM + ka + c);
            float f[4] = {v.x, v.y, v.z, v.w};
            __nv_bfloat16 h0 = __float2bfloat16(f[0]);
            __nv_bfloat16 h1 = __float2bfloat16(f[1]);
            __nv_bfloat16 h2 = __float2bfloat16(f[2]);
            __nv_bfloat16 h3 = __float2bfloat16(f[3]);
            __nv_bfloat162 hp0 = __nv_bfloat162(h0, h1);
            __nv_bfloat162 hp1 = __nv_bfloat162(h2, h3);
            __nv_bfloat162 lp0 = __nv_bfloat162(__float2bfloat16(f[0] - __bfloat162float(h0)),
                                                __float2bfloat16(f[1] - __bfloat162float(h1)));
            __nv_bfloat162 lp1 = __nv_bfloat162(__float2bfloat16(f[2] - __bfloat162float(h2)),
                                                __float2bfloat16(f[3] - __bfloat162float(h3)));
            *reinterpret_cast<__nv_bfloat162*>(&Ah[r * LDA + c])     = hp0;
            *reinterpret_cast<__nv_bfloat162*>(&Ah[r * LDA + c + 2]) = hp1;
            *reinterpret_cast<__nv_bfloat162*>(&Al[r * LDA + c])     = lp0;
            *reinterpret_cast<__nv_bfloat162*>(&Al[r * LDA + c + 2]) = lp1;
        }
        #pragma unroll
        for (int l = 0; l < 4; l++) {
            int idx = tid + l * 256;
            int r = idx >> 5;
            int c = (idx & 31) * 4;
            uint2 vh = *reinterpret_cast<const uint2*>(&g_Wh[(size_t)(k0 + r) * 128 + c]);
            uint2 vl = *reinterpret_cast<const uint2*>(&g_Wl[(size_t)(k0 + r) * 128 + c]);
            *reinterpret_cast<uint2*>(&Bh[r * LDB + c]) = vh;
            *reinterpret_cast<uint2*>(&Bl[r * LDB + c]) = vl;
        }
        __syncthreads();

        #pragma unroll
        for (int ks = 0; ks < 2; ks++) {
            uint32_t ah[2][4], al[2][4], bh[4][2], bl[4][2];
            #pragma unroll
            for (int mt = 0; mt < 2; mt++) {
                int r = wm + mt * 16 + (lane & 15);
                int eo = r * LDA + ks * 16 + ((lane >> 4) * 8);
                uint32_t ad = s2u(&Ah[eo]);
                asm volatile("ldmatrix.sync.aligned.m8n8.x4.shared.b16 {%0,%1,%2,%3}, [%4];"
                             : "=r"(ah[mt][0]), "=r"(ah[mt][1]), "=r"(ah[mt][2]), "=r"(ah[mt][3])
                             : "r"(ad));
                uint32_t ad2 = s2u(&Al[eo]);
                asm volatile("ldmatrix.sync.aligned.m8n8.x4.shared.b16 {%0,%1,%2,%3}, [%4];"
                             : "=r"(al[mt][0]), "=r"(al[mt][1]), "=r"(al[mt][2]), "=r"(al[mt][3])
                             : "r"(ad2));
            }
            #pragma unroll
            for (int nt = 0; nt < 4; nt++) {
                int kr = ks * 16 + (lane & 15);
                int eo = kr * LDB + wn + nt * 8;
                uint32_t bd = s2u(&Bh[eo]);
                asm volatile("ldmatrix.sync.aligned.m8n8.x2.trans.shared.b16 {%0,%1}, [%2];"
                             : "=r"(bh[nt][0]), "=r"(bh[nt][1]) : "r"(bd));
                uint32_t bd2 = s2u(&Bl[eo]);
                asm volatile("ldmatrix.sync.aligned.m8n8.x2.trans.shared.b16 {%0,%1}, [%2];"
                             : "=r"(bl[nt][0]), "=r"(bl[nt][1]) : "r"(bd2));
            }
            #pragma unroll
            for (int mt = 0; mt < 2; mt++)
                #pragma unroll
                for (int nt = 0; nt < 4; nt++) {
                    MMA_B16(acc[mt][nt], ah[mt], bh[nt]);
                    MMA_B16(acc[mt][nt], ah[mt], bl[nt]);
                    MMA_B16(acc[mt][nt], al[mt], bh[nt]);
                }
        }
        __syncthreads();
    }

    #pragma unroll
    for (int mt = 0; mt < 2; mt++) {
        int r0 = row0 + wm + mt * 16 + (lane >> 2);
        #pragma unroll
        for (int nt = 0; nt < 4; nt++) {
            int col = wn + nt * 8 + (lane & 3) * 2;
            if (ADD_PARTIAL) {
                float b0 = g_b[col], b1 = g_b[col + 1];
                if (r0 < M) {
                    float2 p = *reinterpret_cast<const float2*>(&g_partial[(size_t)r0 * DIM + col]);
                    float2 o;
                    o.x = fmaxf(acc[mt][nt][0] + p.x + b0, 0.f);
                    o.y = fmaxf(acc[mt][nt][1] + p.y + b1, 0.f);
                    *reinterpret_cast<float2*>(&outp[(size_t)r0 * DIM + col]) = o;
                }
                int r1 = r0 + 8;
                if (r1 < M) {
                    float2 p = *reinterpret_cast<const float2*>(&g_partial[(size_t)r1 * DIM + col]);
                    float2 o;
                    o.x = fmaxf(acc[mt][nt][2] + p.x + b0, 0.f);
                    o.y = fmaxf(acc[mt][nt][3] + p.y + b1, 0.f);
                    *reinterpret_cast<float2*>(&outp[(size_t)r1 * DIM + col]) = o;
                }
            } else {
                if (r0 < M)
                    *reinterpret_cast<float2*>(&outp[(size_t)r0 * DIM + col]) =
                        make_float2(acc[mt][nt][0], acc[mt][nt][1]);
                int r1 = r0 + 8;
                if (r1 < M)
                    *reinterpret_cast<float2*>(&outp[(size_t)r1 * DIM + col]) =
                        make_float2(acc[mt][nt][2], acc[mt][nt][3]);
            }
        }
    }
}

// Stream B: partial = h @ W[0:128]
__global__ __launch_bounds__(256, 3) void gemm_h(const float* __restrict__ h, int M) {
    gemm_half<false>(h, g_partial, M, 0, 4, 0);
}

// out = relu(partial + msg @ W[128:256] + b) over a block range
__global__ __launch_bounds__(256, 3) void gemm_msg(float* __restrict__ out, int M, int blk0) {
    gemm_half<true>(g_msg, out, M, 4, 8, blk0);
}

// ---------------------------------------------------------------------------
extern "C" void kernel_launch(void* const* d_in, const int* in_sizes, int n_in,
                              void* d_out, int out_size) {
    const float* h  = (const float*)d_in[0];
    const int* src  = (const int*)d_in[1];
    const int* dst  = (const int*)d_in[2];
    const float* W1 = (const float*)d_in[3];
    const float* b1 = (const float*)d_in[4];
    const float* W2 = (const float*)d_in[5];
    const float* b2 = (const float*)d_in[6];
    float* out = (float*)d_out;

    int N = in_sizes[0] / DIM;
    int E = in_sizes[1];
    int sblocks = (N + SCAN_BLK - 1) / SCAN_BLK;

    // Node split for the gather/gemm pipeline (64-aligned)
    int Nh = ((N / 2 + GBM - 1) / GBM) * GBM;        // 25024
    if (Nh > N) Nh = N;
    int blocks1 = Nh / GBM;                           // 391
    int blocks2 = (N - Nh + GBM - 1) / GBM;           // 391

    cudaStream_t sB;
    cudaEvent_t eFork, eG1, eG2, eB2;
    cudaStreamCreateWithFlags(&sB, cudaStreamNonBlocking);
    cudaEventCreateWithFlags(&eFork, cudaEventDisableTiming);
    cudaEventCreateWithFlags(&eG1, cudaEventDisableTiming);
    cudaEventCreateWithFlags(&eG2, cudaEventDisableTiming);
    cudaEventCreateWithFlags(&eB2, cudaEventDisableTiming);

    cudaEventRecord(eFork, 0);
    cudaStreamWaitEvent(sB, eFork, 0);

    // Stream B: weight fusion + h-half GEMM (independent of aggregation)
    fuse_weights<<<257, 128, 0, sB>>>(W1, b1, W2, b2);
    gemm_h<<<(N + GBM - 1) / GBM, 256, 0, sB>>>(h, N);

    // Stream A (default): aggregation chain (g_deg/g_flagS are zero by invariant)
    histogram<<<(E + 255) / 256, 256>>>(dst, E);
    scan_onepass<<<sblocks, SCAN_BLK>>>(N);
    fill_csr<<<(E + 255) / 256, 256>>>(src, dst, E);

    long long gt1 = (long long)Nh * 32;
    gather_csr<<<(int)((gt1 + 255) / 256), 256>>>(h, 0, Nh);
    cudaEventRecord(eG1, 0);

    long long gt2 = (long long)(N - Nh) * 32;
    gather_csr<<<(int)((gt2 + 255) / 256), 256>>>(h, Nh, N);
    cudaEventRecord(eG2, 0);

    // Stream B: first-half msg GEMM overlapped with gather(half2),
    // then cleanup (restores zero invariant) overlapped with gemm_msg(half2)
    cudaStreamWaitEvent(sB, eG1, 0);
    gemm_msg<<<blocks1, 256, 0, sB>>>(out, N, 0);
    cudaStreamWaitEvent(sB, eG2, 0);
    cleanup<<<(N + 255) / 256, 256, 0, sB>>>(N);
    cudaEventRecord(eB2, sB);

    // Stream A: second-half msg GEMM, then join stream B
    gemm_msg<<<blocks2, 256>>>(out, N, blocks1);
    cudaStreamWaitEvent(0, eB2, 0);
}